// round 16
// baseline (speedup 1.0000x reference)
#include <cuda_runtime.h>
#include <cuda_bf16.h>
#include <cstdint>

// Problem constants
#define Bb 2048
#define Tt 2048
#define S  16  // SMEM ring steps (4 chunks x 4 steps)
#define C  4   // steps per chunk / commit group
// F=8, U=3, 3U=9

// Scratch (allocation-free rule): only the [t][b] output staging remains —
// prep is fused into the scan, so the 3x192MB gate buffers are GONE.
__device__ float g_outT[(size_t)Tt * Bb];

typedef unsigned long long u64;
typedef unsigned int u32;

// HW tanh (sm_75+)
__device__ __forceinline__ float tanh_fast(float x) {
    float y;
    asm("tanh.approx.f32 %0, %1;" : "=f"(y) : "f"(x));
    return y;
}

// f32x2 packed helpers (Blackwell FFMA2 — ptxas never auto-fuses from C++)
__device__ __forceinline__ u64 pk(float lo, float hi) {
    u64 r;
    asm("mov.b64 %0, {%1,%2};" : "=l"(r) : "f"(lo), "f"(hi));
    return r;
}
__device__ __forceinline__ void upk(u64 v, float& lo, float& hi) {
    asm("mov.b64 {%0,%1}, %2;" : "=f"(lo), "=f"(hi) : "l"(v));
}
__device__ __forceinline__ u64 fma2(u64 a, u64 b, u64 c) {
    u64 d;
    asm("fma.rn.f32x2 %0, %1, %2, %3;" : "=l"(d) : "l"(a), "l"(b), "l"(c));
    return d;
}

// cp.async 16B: completion via commit-group counters
__device__ __forceinline__ void cp16(u32 smem_dst, const void* gsrc) {
    asm volatile("cp.async.cg.shared.global [%0], [%1], 16;"
                 :: "r"(smem_dst), "l"(gsrc) : "memory");
}
__device__ __forceinline__ void cp_commit() {
    asm volatile("cp.async.commit_group;" ::: "memory");
}
template <int N>
__device__ __forceinline__ void cp_wait() {
    asm volatile("cp.async.wait_group %0;" :: "n"(N) : "memory");
}

__device__ __forceinline__ u32 smem_u32(const void* p) {
    u32 a;
    asm("{ .reg .u64 t; cvta.to.shared.u64 t, %1; cvt.u32.u64 %0, t; }"
        : "=r"(a) : "l"(p));
    return a;
}

// ---------------------------------------------------------------------------
// FUSED scan: 64 blocks x 32 threads = 2048 lanes, one batch row per lane.
// Streams x[b][t][0..7] (32B/step, per-lane contiguous) through a chunked
// cp.async SMEM ring (R12 discipline: one wait + one commit per 4-step chunk).
// Computes xw = x@kernel + biases inline with packed FFMA2 (off the h-chain;
// R13 proved the issue slack), then the R12 tanh gate math.
// ---------------------------------------------------------------------------
__global__ void __launch_bounds__(32) scan_kernel(
    const float* __restrict__ x,        // [B][T][8]
    const float* __restrict__ kern,     // [8][9]
    const float* __restrict__ rk,       // [3][9]
    const float* __restrict__ bias_i,   // [9]
    const float* __restrict__ bias_r,   // [9]
    const float* __restrict__ dense_w,  // [3][1]
    const float* __restrict__ dense_b)  // [1]
{
    __shared__ float4 ring[S][2][32];   // 16 KB: 2 float4 of x per lane/stage

    const int tid = threadIdx.x;
    const int b = blockIdx.x * 32 + tid;

    // ---- input-projection weights, column-scaled & packed ----
    // cols 0-5 (z,r gates) pre-scaled by 0.5 (sigmoid-via-tanh), cols 6-8 raw.
    float bsr[9];
#pragma unroll
    for (int j = 0; j < 9; j++) {
        float v = __ldg(bias_i + j) + __ldg(bias_r + j);
        bsr[j] = (j < 6) ? 0.5f * v : v;
    }
    u64 Wx[8][4];    // col pairs (0,1),(2,3),(4,5),(6,7)
    float Wx8[8];    // col 8
#pragma unroll
    for (int f = 0; f < 8; f++) {
#pragma unroll
        for (int p = 0; p < 4; p++) {
            float lo = __ldg(kern + f * 9 + 2 * p);
            float hi = __ldg(kern + f * 9 + 2 * p + 1);
            if (2 * p < 6)     lo *= 0.5f;
            if (2 * p + 1 < 6) hi *= 0.5f;
            Wx[f][p] = pk(lo, hi);
        }
        Wx8[f] = __ldg(kern + f * 9 + 8);
    }
    const u64 B01 = pk(bsr[0], bsr[1]);
    const u64 B23 = pk(bsr[2], bsr[3]);
    const u64 B45 = pk(bsr[4], bsr[5]);
    const u64 B67 = pk(bsr[6], bsr[7]);
    const float B8 = bsr[8];

    // ---- recurrent weights, z/r cols pre-halved (R12) ----
    float K[3][9];
#pragma unroll
    for (int u = 0; u < 3; u++)
#pragma unroll
        for (int j = 0; j < 9; j++) {
            float v = __ldg(rk + u * 9 + j);
            K[u][j] = (j < 6) ? 0.5f * v : v;
        }

    // dense_w pre-doubled: out = halfm*dot(h,2w)+db == m*dot(h,w)+db
    const float w0 = 2.0f * __ldg(dense_w);
    const float w1 = 2.0f * __ldg(dense_w + 1);
    const float w2 = 2.0f * __ldg(dense_w + 2);
    const float db = __ldg(dense_b);

    float h0 = 0.0f, h1 = 0.0f, h2 = 0.0f;

    const float* gx = x + (size_t)b * Tt * 8;   // this lane's row
    const u32 sbase = smem_u32(ring) + (tid << 4);
    char* const rbase = (char*)ring + (tid << 4);
    // addr(stage st, q) = sbase + ((st*2+q) << 9)

    // prologue: chunks 0..3 (steps 0..15), one commit per chunk
#pragma unroll
    for (int c = 0; c < S / C; c++) {
#pragma unroll
        for (int s = 0; s < C; s++) {
            const int st = c * C + s;
            cp16(sbase + ((u32)(st * 2) << 9),       gx + (size_t)st * 8);
            cp16(sbase + ((u32)(st * 2 + 1) << 9),   gx + (size_t)st * 8 + 4);
        }
        cp_commit();
    }

    // chunk 0 resident: committed=4, need group0 -> pending<=3
    cp_wait<3>();
    float4 nx0 = *reinterpret_cast<float4*>(rbase + (0 << 9));
    float4 nx1 = *reinterpret_cast<float4*>(rbase + (1 << 9));

    for (int c = 0; c < Tt / C; c++) {
        const int base_t = c * C;
#pragma unroll
        for (int s = 0; s < C; s++) {
            const int tc = base_t + s;
            const int ns = (tc + 1) & (S - 1);   // next stage

            const float4 a = nx0;
            const float4 d = nx1;

            // chunk boundary: ensure chunk c+1 resident
            // committed = 4+c, need group c+1 done -> pending <= 2
            if (s == C - 1) cp_wait<2>();

            nx0 = *reinterpret_cast<float4*>(rbase + (size_t)(ns * 2) * 512);
            nx1 = *reinterpret_cast<float4*>(rbase + (size_t)(ns * 2 + 1) * 512);

            // refill this chunk's slot with chunk c+4 (clamp t: x not padded)
            if (s == C - 1) {
                const int slot = c & 3;
#pragma unroll
                for (int q = 0; q < C; q++) {
                    const int st = slot * C + q;
                    int tp = base_t + S + q;
                    if (tp > Tt - 1) tp = Tt - 1;   // clamped, always in-bounds
                    cp16(sbase + ((u32)(st * 2) << 9),     gx + (size_t)tp * 8);
                    cp16(sbase + ((u32)(st * 2 + 1) << 9), gx + (size_t)tp * 8 + 4);
                }
                cp_commit();
            }

            const float xf[8] = {a.x, a.y, a.z, a.w, d.x, d.y, d.z, d.w};

            // mask: any(x != 0) -> halfm in {0, 0.5}
            float sabs = fabsf(xf[0]);
#pragma unroll
            for (int f = 1; f < 8; f++) sabs += fabsf(xf[f]);
            const float halfm = (sabs != 0.0f) ? 0.5f : 0.0f;

            // xw (packed, off the h-chain): pre-activation inputs
            u64 a01 = B01, a23 = B23, a45 = B45, a67 = B67;
            float a8 = B8;
#pragma unroll
            for (int f = 0; f < 8; f++) {
                const u64 xp = pk(xf[f], xf[f]);
                a01 = fma2(xp, Wx[f][0], a01);
                a23 = fma2(xp, Wx[f][1], a23);
                a45 = fma2(xp, Wx[f][2], a45);
                a67 = fma2(xp, Wx[f][3], a67);
                a8  = fmaf(xf[f], Wx8[f], a8);
            }
            float xz0, xz1, xz2, xr0, xr1, xr2, xh0, xh1;
            upk(a01, xz0, xz1);
            upk(a23, xz2, xr0);
            upk(a45, xr1, xr2);
            upk(a67, xh0, xh1);
            const float xh2 = a8;

            // ---- R12 gate math (tanh gates; best-known scan body) ----
            const float az0 = fmaf(h2, K[2][0], fmaf(h1, K[1][0], fmaf(h0, K[0][0], xz0)));
            const float az1 = fmaf(h2, K[2][1], fmaf(h1, K[1][1], fmaf(h0, K[0][1], xz1)));
            const float az2 = fmaf(h2, K[2][2], fmaf(h1, K[1][2], fmaf(h0, K[0][2], xz2)));
            const float ar0 = fmaf(h2, K[2][3], fmaf(h1, K[1][3], fmaf(h0, K[0][3], xr0)));
            const float ar1 = fmaf(h2, K[2][4], fmaf(h1, K[1][4], fmaf(h0, K[0][4], xr1)));
            const float ar2 = fmaf(h2, K[2][5], fmaf(h1, K[1][5], fmaf(h0, K[0][5], xr2)));
            const float hh0 = fmaf(h2, K[2][6], fmaf(h1, K[1][6], h0 * K[0][6]));
            const float hh1 = fmaf(h2, K[2][7], fmaf(h1, K[1][7], h0 * K[0][7]));
            const float hh2 = fmaf(h2, K[2][8], fmaf(h1, K[1][8], h0 * K[0][8]));

            const float tz0 = tanh_fast(az0);
            const float tz1 = tanh_fast(az1);
            const float tz2 = tanh_fast(az2);
            const float tr0 = tanh_fast(ar0);
            const float tr1 = tanh_fast(ar1);
            const float tr2 = tanh_fast(ar2);

            // g = m*(1-z) = halfm*(1 - tanh(a_z/2))
            const float g0 = fmaf(-halfm, tz0, halfm);
            const float g1 = fmaf(-halfm, tz1, halfm);
            const float g2 = fmaf(-halfm, tz2, halfm);

            // r = 0.5 + 0.5*tanh(a_r/2)
            const float r0 = fmaf(tr0, 0.5f, 0.5f);
            const float r1 = fmaf(tr1, 0.5f, 0.5f);
            const float r2 = fmaf(tr2, 0.5f, 0.5f);

            const float hc0 = tanh_fast(fmaf(r0, hh0, xh0));
            const float hc1 = tanh_fast(fmaf(r1, hh1, xh1));
            const float hc2 = tanh_fast(fmaf(r2, hh2, xh2));

            // h_new = h + g*(hc - h)
            h0 = fmaf(g0, hc0 - h0, h0);
            h1 = fmaf(g1, hc1 - h1, h1);
            h2 = fmaf(g2, hc2 - h2, h2);

            // out = halfm * dot(h_new, 2w) + db
            const float dot = fmaf(h2, w2, fmaf(h1, w1, h0 * w0));
            g_outT[(size_t)tc * Bb + b] = fmaf(halfm, dot, db);
        }
    }
}

// ---------------------------------------------------------------------------
// Transpose g_outT[t][b] -> out[b][t]
// ---------------------------------------------------------------------------
__global__ void transpose_kernel(float* __restrict__ out) {
    __shared__ float tile[32][33];
    const int bBase = blockIdx.x * 32;
    const int tBase = blockIdx.y * 32;

    tile[threadIdx.y][threadIdx.x] =
        g_outT[(size_t)(tBase + threadIdx.y) * Bb + (bBase + threadIdx.x)];
    __syncthreads();
    out[(size_t)(bBase + threadIdx.y) * Tt + (tBase + threadIdx.x)] =
        tile[threadIdx.x][threadIdx.y];
}

// ---------------------------------------------------------------------------
extern "C" void kernel_launch(void* const* d_in, const int* in_sizes, int n_in,
                              void* d_out, int out_size) {
    const float* x       = (const float*)d_in[0];  // (B,T,8)
    const float* kern    = (const float*)d_in[1];  // (8,9)
    const float* rk      = (const float*)d_in[2];  // (3,9)
    const float* bias_i  = (const float*)d_in[3];  // (9,)
    const float* bias_r  = (const float*)d_in[4];  // (9,)
    const float* dense_w = (const float*)d_in[5];  // (3,1)
    const float* dense_b = (const float*)d_in[6];  // (1,)
    float* out = (float*)d_out;                    // (B,T,1)

    (void)in_sizes; (void)n_in; (void)out_size;

    scan_kernel<<<Bb / 32, 32>>>(x, kern, rk, bias_i, bias_r, dense_w, dense_b);

    dim3 gC(Bb / 32, Tt / 32);
    transpose_kernel<<<gC, dim3(32, 32)>>>(out);
}

// round 17
// speedup vs baseline: 1.0004x; 1.0004x over previous
#include <cuda_runtime.h>
#include <cuda_bf16.h>
#include <cstdint>

// Problem constants
#define Bb 2048
#define Tt 2048
#define S  16  // SMEM ring steps (4 chunks x 4 steps)
#define C  4   // steps per chunk / commit group
// F=8, U=3, 3U=9

// Scratch (allocation-free rule): only the [t][b] output staging remains —
// prep is fused into the scan, so the 3x192MB gate buffers are GONE.
__device__ float g_outT[(size_t)Tt * Bb];

typedef unsigned long long u64;
typedef unsigned int u32;

// HW tanh (sm_75+)
__device__ __forceinline__ float tanh_fast(float x) {
    float y;
    asm("tanh.approx.f32 %0, %1;" : "=f"(y) : "f"(x));
    return y;
}

// f32x2 packed helpers (Blackwell FFMA2 — ptxas never auto-fuses from C++)
__device__ __forceinline__ u64 pk(float lo, float hi) {
    u64 r;
    asm("mov.b64 %0, {%1,%2};" : "=l"(r) : "f"(lo), "f"(hi));
    return r;
}
__device__ __forceinline__ void upk(u64 v, float& lo, float& hi) {
    asm("mov.b64 {%0,%1}, %2;" : "=f"(lo), "=f"(hi) : "l"(v));
}
__device__ __forceinline__ u64 fma2(u64 a, u64 b, u64 c) {
    u64 d;
    asm("fma.rn.f32x2 %0, %1, %2, %3;" : "=l"(d) : "l"(a), "l"(b), "l"(c));
    return d;
}

// cp.async 16B: completion via commit-group counters
__device__ __forceinline__ void cp16(u32 smem_dst, const void* gsrc) {
    asm volatile("cp.async.cg.shared.global [%0], [%1], 16;"
                 :: "r"(smem_dst), "l"(gsrc) : "memory");
}
__device__ __forceinline__ void cp_commit() {
    asm volatile("cp.async.commit_group;" ::: "memory");
}
template <int N>
__device__ __forceinline__ void cp_wait() {
    asm volatile("cp.async.wait_group %0;" :: "n"(N) : "memory");
}

__device__ __forceinline__ u32 smem_u32(const void* p) {
    u32 a;
    asm("{ .reg .u64 t; cvta.to.shared.u64 t, %1; cvt.u32.u64 %0, t; }"
        : "=r"(a) : "l"(p));
    return a;
}

// ---------------------------------------------------------------------------
// FUSED scan: 64 blocks x 32 threads = 2048 lanes, one batch row per lane.
// Streams x[b][t][0..7] (32B/step, per-lane contiguous) through a chunked
// cp.async SMEM ring (R12 discipline: one wait + one commit per 4-step chunk).
// Computes xw = x@kernel + biases inline with packed FFMA2 (off the h-chain;
// R13 proved the issue slack), then the R12 tanh gate math.
// ---------------------------------------------------------------------------
__global__ void __launch_bounds__(32) scan_kernel(
    const float* __restrict__ x,        // [B][T][8]
    const float* __restrict__ kern,     // [8][9]
    const float* __restrict__ rk,       // [3][9]
    const float* __restrict__ bias_i,   // [9]
    const float* __restrict__ bias_r,   // [9]
    const float* __restrict__ dense_w,  // [3][1]
    const float* __restrict__ dense_b)  // [1]
{
    __shared__ float4 ring[S][2][32];   // 16 KB: 2 float4 of x per lane/stage

    const int tid = threadIdx.x;
    const int b = blockIdx.x * 32 + tid;

    // ---- input-projection weights, column-scaled & packed ----
    // cols 0-5 (z,r gates) pre-scaled by 0.5 (sigmoid-via-tanh), cols 6-8 raw.
    float bsr[9];
#pragma unroll
    for (int j = 0; j < 9; j++) {
        float v = __ldg(bias_i + j) + __ldg(bias_r + j);
        bsr[j] = (j < 6) ? 0.5f * v : v;
    }
    u64 Wx[8][4];    // col pairs (0,1),(2,3),(4,5),(6,7)
    float Wx8[8];    // col 8
#pragma unroll
    for (int f = 0; f < 8; f++) {
#pragma unroll
        for (int p = 0; p < 4; p++) {
            float lo = __ldg(kern + f * 9 + 2 * p);
            float hi = __ldg(kern + f * 9 + 2 * p + 1);
            if (2 * p < 6)     lo *= 0.5f;
            if (2 * p + 1 < 6) hi *= 0.5f;
            Wx[f][p] = pk(lo, hi);
        }
        Wx8[f] = __ldg(kern + f * 9 + 8);
    }
    const u64 B01 = pk(bsr[0], bsr[1]);
    const u64 B23 = pk(bsr[2], bsr[3]);
    const u64 B45 = pk(bsr[4], bsr[5]);
    const u64 B67 = pk(bsr[6], bsr[7]);
    const float B8 = bsr[8];

    // ---- recurrent weights, z/r cols pre-halved (R12) ----
    float K[3][9];
#pragma unroll
    for (int u = 0; u < 3; u++)
#pragma unroll
        for (int j = 0; j < 9; j++) {
            float v = __ldg(rk + u * 9 + j);
            K[u][j] = (j < 6) ? 0.5f * v : v;
        }

    // dense_w pre-doubled: out = halfm*dot(h,2w)+db == m*dot(h,w)+db
    const float w0 = 2.0f * __ldg(dense_w);
    const float w1 = 2.0f * __ldg(dense_w + 1);
    const float w2 = 2.0f * __ldg(dense_w + 2);
    const float db = __ldg(dense_b);

    float h0 = 0.0f, h1 = 0.0f, h2 = 0.0f;

    const float* gx = x + (size_t)b * Tt * 8;   // this lane's row
    const u32 sbase = smem_u32(ring) + (tid << 4);
    char* const rbase = (char*)ring + (tid << 4);
    // addr(stage st, q) = sbase + ((st*2+q) << 9)

    // prologue: chunks 0..3 (steps 0..15), one commit per chunk
#pragma unroll
    for (int c = 0; c < S / C; c++) {
#pragma unroll
        for (int s = 0; s < C; s++) {
            const int st = c * C + s;
            cp16(sbase + ((u32)(st * 2) << 9),       gx + (size_t)st * 8);
            cp16(sbase + ((u32)(st * 2 + 1) << 9),   gx + (size_t)st * 8 + 4);
        }
        cp_commit();
    }

    // chunk 0 resident: committed=4, need group0 -> pending<=3
    cp_wait<3>();
    float4 nx0 = *reinterpret_cast<float4*>(rbase + (0 << 9));
    float4 nx1 = *reinterpret_cast<float4*>(rbase + (1 << 9));

    for (int c = 0; c < Tt / C; c++) {
        const int base_t = c * C;
#pragma unroll
        for (int s = 0; s < C; s++) {
            const int tc = base_t + s;
            const int ns = (tc + 1) & (S - 1);   // next stage

            const float4 a = nx0;
            const float4 d = nx1;

            // chunk boundary: ensure chunk c+1 resident
            // committed = 4+c, need group c+1 done -> pending <= 2
            if (s == C - 1) cp_wait<2>();

            nx0 = *reinterpret_cast<float4*>(rbase + (size_t)(ns * 2) * 512);
            nx1 = *reinterpret_cast<float4*>(rbase + (size_t)(ns * 2 + 1) * 512);

            // refill this chunk's slot with chunk c+4 (clamp t: x not padded)
            if (s == C - 1) {
                const int slot = c & 3;
#pragma unroll
                for (int q = 0; q < C; q++) {
                    const int st = slot * C + q;
                    int tp = base_t + S + q;
                    if (tp > Tt - 1) tp = Tt - 1;   // clamped, always in-bounds
                    cp16(sbase + ((u32)(st * 2) << 9),     gx + (size_t)tp * 8);
                    cp16(sbase + ((u32)(st * 2 + 1) << 9), gx + (size_t)tp * 8 + 4);
                }
                cp_commit();
            }

            const float xf[8] = {a.x, a.y, a.z, a.w, d.x, d.y, d.z, d.w};

            // mask: any(x != 0) -> halfm in {0, 0.5}
            float sabs = fabsf(xf[0]);
#pragma unroll
            for (int f = 1; f < 8; f++) sabs += fabsf(xf[f]);
            const float halfm = (sabs != 0.0f) ? 0.5f : 0.0f;

            // xw (packed, off the h-chain): pre-activation inputs
            u64 a01 = B01, a23 = B23, a45 = B45, a67 = B67;
            float a8 = B8;
#pragma unroll
            for (int f = 0; f < 8; f++) {
                const u64 xp = pk(xf[f], xf[f]);
                a01 = fma2(xp, Wx[f][0], a01);
                a23 = fma2(xp, Wx[f][1], a23);
                a45 = fma2(xp, Wx[f][2], a45);
                a67 = fma2(xp, Wx[f][3], a67);
                a8  = fmaf(xf[f], Wx8[f], a8);
            }
            float xz0, xz1, xz2, xr0, xr1, xr2, xh0, xh1;
            upk(a01, xz0, xz1);
            upk(a23, xz2, xr0);
            upk(a45, xr1, xr2);
            upk(a67, xh0, xh1);
            const float xh2 = a8;

            // ---- R12 gate math (tanh gates; best-known scan body) ----
            const float az0 = fmaf(h2, K[2][0], fmaf(h1, K[1][0], fmaf(h0, K[0][0], xz0)));
            const float az1 = fmaf(h2, K[2][1], fmaf(h1, K[1][1], fmaf(h0, K[0][1], xz1)));
            const float az2 = fmaf(h2, K[2][2], fmaf(h1, K[1][2], fmaf(h0, K[0][2], xz2)));
            const float ar0 = fmaf(h2, K[2][3], fmaf(h1, K[1][3], fmaf(h0, K[0][3], xr0)));
            const float ar1 = fmaf(h2, K[2][4], fmaf(h1, K[1][4], fmaf(h0, K[0][4], xr1)));
            const float ar2 = fmaf(h2, K[2][5], fmaf(h1, K[1][5], fmaf(h0, K[0][5], xr2)));
            const float hh0 = fmaf(h2, K[2][6], fmaf(h1, K[1][6], h0 * K[0][6]));
            const float hh1 = fmaf(h2, K[2][7], fmaf(h1, K[1][7], h0 * K[0][7]));
            const float hh2 = fmaf(h2, K[2][8], fmaf(h1, K[1][8], h0 * K[0][8]));

            const float tz0 = tanh_fast(az0);
            const float tz1 = tanh_fast(az1);
            const float tz2 = tanh_fast(az2);
            const float tr0 = tanh_fast(ar0);
            const float tr1 = tanh_fast(ar1);
            const float tr2 = tanh_fast(ar2);

            // g = m*(1-z) = halfm*(1 - tanh(a_z/2))
            const float g0 = fmaf(-halfm, tz0, halfm);
            const float g1 = fmaf(-halfm, tz1, halfm);
            const float g2 = fmaf(-halfm, tz2, halfm);

            // r = 0.5 + 0.5*tanh(a_r/2)
            const float r0 = fmaf(tr0, 0.5f, 0.5f);
            const float r1 = fmaf(tr1, 0.5f, 0.5f);
            const float r2 = fmaf(tr2, 0.5f, 0.5f);

            const float hc0 = tanh_fast(fmaf(r0, hh0, xh0));
            const float hc1 = tanh_fast(fmaf(r1, hh1, xh1));
            const float hc2 = tanh_fast(fmaf(r2, hh2, xh2));

            // h_new = h + g*(hc - h)
            h0 = fmaf(g0, hc0 - h0, h0);
            h1 = fmaf(g1, hc1 - h1, h1);
            h2 = fmaf(g2, hc2 - h2, h2);

            // out = halfm * dot(h_new, 2w) + db
            const float dot = fmaf(h2, w2, fmaf(h1, w1, h0 * w0));
            g_outT[(size_t)tc * Bb + b] = fmaf(halfm, dot, db);
        }
    }
}

// ---------------------------------------------------------------------------
// Transpose g_outT[t][b] -> out[b][t]
// ---------------------------------------------------------------------------
__global__ void transpose_kernel(float* __restrict__ out) {
    __shared__ float tile[32][33];
    const int bBase = blockIdx.x * 32;
    const int tBase = blockIdx.y * 32;

    tile[threadIdx.y][threadIdx.x] =
        g_outT[(size_t)(tBase + threadIdx.y) * Bb + (bBase + threadIdx.x)];
    __syncthreads();
    out[(size_t)(bBase + threadIdx.y) * Tt + (tBase + threadIdx.x)] =
        tile[threadIdx.x][threadIdx.y];
}

// ---------------------------------------------------------------------------
extern "C" void kernel_launch(void* const* d_in, const int* in_sizes, int n_in,
                              void* d_out, int out_size) {
    const float* x       = (const float*)d_in[0];  // (B,T,8)
    const float* kern    = (const float*)d_in[1];  // (8,9)
    const float* rk      = (const float*)d_in[2];  // (3,9)
    const float* bias_i  = (const float*)d_in[3];  // (9,)
    const float* bias_r  = (const float*)d_in[4];  // (9,)
    const float* dense_w = (const float*)d_in[5];  // (3,1)
    const float* dense_b = (const float*)d_in[6];  // (1,)
    float* out = (float*)d_out;                    // (B,T,1)

    (void)in_sizes; (void)n_in; (void)out_size;

    scan_kernel<<<Bb / 32, 32>>>(x, kern, rk, bias_i, bias_r, dense_w, dense_b);

    dim3 gC(Bb / 32, Tt / 32);
    transpose_kernel<<<gC, dim3(32, 32)>>>(out);
}